// round 11
// baseline (speedup 1.0000x reference)
#include <cuda_runtime.h>
#include <cuda_bf16.h>
#include <cstdint>

// Fused (HMMA mma.sync bf16, 3-term split for fp32-grade accuracy):
// out = LeakyReLU([x_up, LeakyReLU(gather(x_down)@W_lin + b_lin)] @ W_fus + b_fus)
// Identity: MLP(gather(x)) == gather(MLP(x)) -> down-MLP computed once (4x less work).
// R11: k32 column-half ring pipeline. W/A 32KB slots double as 2-deep rings at k32
// granularity (column halves of 128B-row swizzled images are disjoint); x_up/x_down
// prefetched fp32 via cp.async into X0/X1 and converted smem->smem. One sync/step.
// NOTE: harness ptxas targets sm_103 (no 'a') -> tcgen05 unavailable; use mma.sync.

#define N_UP    65536
#define N_DOWN  16384
#define C_UP    128

#define M_TILE  128
#define THREADS 256

#define SWZ(x) ((x) ^ ((((uint32_t)(x)) >> 3) & 0x70))

// ---------------- SMEM layout (bytes) ----------------
#define OFF_B    0                        // bias[128] fp32
#define OFF_WH   1024
#define OFF_WL   (OFF_WH + 16384)
#define OFF_AH   (OFF_WL + 16384)
#define OFF_AL   (OFF_AH + 16384)
#define OFF_X0   (OFF_AL + 16384)        // fp32 k32 chunk staging (16KB)
#define OFF_X1   (OFF_X0 + 16384)
#define SMEM_TOTAL (OFF_X1 + 16384)      // 99328 (~97KB) -> 2 CTAs/SM

// ---------------- device scratch ----------------
// Pre-split, pre-swizzled weight tile images: [layer][split][k64-chunk][16KB]
// Image layout: [n 0..127][k 0..63] bf16, 128B rows, SW128 swizzled.
__device__ __align__(16) unsigned char gW[2][2][4][16384];
// Down-MLP output y, pre-split bf16 hi/lo, row-major [B*N_DOWN][128] (uint32 = bf16x2)
__device__ __align__(16) unsigned int gY_hi[4194304];
__device__ __align__(16) unsigned int gY_lo[4194304];

// ---------------- helpers ----------------
__device__ __forceinline__ uint32_t smem_u32(const void* p) {
    uint32_t a;
    asm("{ .reg .u64 t; cvta.to.shared.u64 t, %1; cvt.u32.u64 %0, t; }" : "=r"(a) : "l"(p));
    return a;
}
__device__ __forceinline__ float bf16r(float x) {
    return __bfloat162float(__float2bfloat16(x));
}
__device__ __forceinline__ uint32_t pack_bf16x2(float lo, float hi) {
    uint32_t d;
    asm("cvt.rn.bf16x2.f32 %0, %1, %2;" : "=r"(d) : "f"(hi), "f"(lo));
    return d;
}
__device__ __forceinline__ void ldmx4(uint32_t* r, uint32_t a) {
    asm volatile("ldmatrix.sync.aligned.m8n8.x4.shared.b16 {%0,%1,%2,%3}, [%4];"
                 : "=r"(r[0]), "=r"(r[1]), "=r"(r[2]), "=r"(r[3]) : "r"(a));
}
__device__ __forceinline__ void mma_bf16(float* c, const uint32_t* a, uint32_t b0, uint32_t b1) {
    asm volatile("mma.sync.aligned.m16n8k16.row.col.f32.bf16.bf16.f32 "
                 "{%0,%1,%2,%3}, {%4,%5,%6,%7}, {%8,%9}, {%0,%1,%2,%3};"
                 : "+f"(c[0]), "+f"(c[1]), "+f"(c[2]), "+f"(c[3])
                 : "r"(a[0]), "r"(a[1]), "r"(a[2]), "r"(a[3]), "r"(b0), "r"(b1));
}
__device__ __forceinline__ void cp16(uint32_t dst, const void* src) {
    asm volatile("cp.async.cg.shared.global [%0], [%1], 16;" :: "r"(dst), "l"(src) : "memory");
}
__device__ __forceinline__ void cp_commit() {
    asm volatile("cp.async.commit_group;" ::: "memory");
}
template <int N>
__device__ __forceinline__ void cp_wait() {
    asm volatile("cp.async.wait_group %0;" :: "n"(N) : "memory");
}

// ---------------- prep ----------------
__global__ void prep_weights(const float* __restrict__ W_lin, const float* __restrict__ W_fus) {
    int tid = blockIdx.x * blockDim.x + threadIdx.x;
    for (int e = tid; e < 2 * 128 * 256; e += gridDim.x * blockDim.x) {
        int L = e >> 15;
        int r = e & 32767;
        int n = r >> 8;          // output col (N), 0..127
        int k = r & 255;         // K, 0..255
        const float* W = L ? W_fus : W_lin;
        float w = W[k * 128 + n];
        float h = bf16r(w);
        float l = w - h;
        int c = k >> 6, kk = k & 63;
        uint32_t a = SWZ((uint32_t)(n * 128 + kk * 2));
        *(unsigned short*)&gW[L][0][c][a] = __bfloat16_as_ushort(__float2bfloat16(h));
        *(unsigned short*)&gW[L][1][c][a] = __bfloat16_as_ushort(__float2bfloat16(l));
    }
}

// ---------------- k32 staging ----------------
// W piece: source gW[layer][*][chunk] column half `half` -> W slot same column half.
__device__ __forceinline__ void stage_W32(uint32_t sb, int layer, int chunk, int half, int t) {
    int n = t >> 1, q = t & 1;
    uint32_t c0 = (uint32_t)(n * 128 + half * 64 + q * 32);
    uint32_t o0 = SWZ(c0), o1 = SWZ(c0 + 16);
    const char* sh = (const char*)&gW[layer][0][chunk][0];
    const char* sl = (const char*)&gW[layer][1][chunk][0];
    cp16(sb + OFF_WH + o0, sh + o0);
    cp16(sb + OFF_WH + o1, sh + o1);
    cp16(sb + OFF_WL + o0, sl + o0);
    cp16(sb + OFF_WL + o1, sl + o1);
}

// y gather k32 slice s (cols 32s..32s+31) -> A slot half (s&1).
__device__ __forceinline__ void stage_Y32(uint32_t sb, int yrow, int s, int t) {
    int srow = t >> 1, q = t & 1;
    size_t boff = (size_t)yrow * 256 + s * 64 + q * 32;
    const char* sh = (const char*)gY_hi + boff;
    const char* sl = (const char*)gY_lo + boff;
    uint32_t c0 = (uint32_t)(srow * 128 + (s & 1) * 64 + q * 32);
    uint32_t o0 = SWZ(c0), o1 = SWZ(c0 + 16);
    cp16(sb + OFF_AH + o0, sh);
    cp16(sb + OFF_AH + o1, sh + 16);
    cp16(sb + OFF_AL + o0, sl);
    cp16(sb + OFF_AL + o1, sl + 16);
}

// fp32 k32 chunk j of src (rowstride_f floats/row) -> X slot (plain layout).
__device__ __forceinline__ void stage_X32(uint32_t sb, int offX, const float* src0,
                                          int rowstride_f, int j, int t) {
    int srow = t >> 1, q = t & 1;
    const char* src = (const char*)(src0 + (size_t)srow * rowstride_f + j * 32 + q * 16);
    uint32_t dst = sb + offX + srow * 128 + q * 64;
#pragma unroll
    for (int i = 0; i < 4; i++) cp16(dst + 16 * i, src + 16 * i);
}

// Convert X slot fp32 [128][32] -> split bf16 into A slot column half `half`.
__device__ __forceinline__ void convert32(char* smem, int offX, int half, int t) {
    int srow = t >> 1, q = t & 1;
    const float4* src = (const float4*)(smem + offX + srow * 128 + q * 64);
#pragma unroll
    for (int i = 0; i < 4; i++) {
        float4 v = src[i];
        float hx = bf16r(v.x), hy = bf16r(v.y), hz = bf16r(v.z), hw = bf16r(v.w);
        uint32_t a = SWZ((uint32_t)(srow * 128 + half * 64 + q * 32 + 8 * i));
        *(uint2*)(smem + OFF_AH + a) = make_uint2(pack_bf16x2(hx, hy), pack_bf16x2(hz, hw));
        *(uint2*)(smem + OFF_AL + a) = make_uint2(pack_bf16x2(v.x - hx, v.y - hy),
                                                  pack_bf16x2(v.z - hz, v.w - hw));
    }
}

// ---------------- k32 compute: acc += A(128 x k32) * W(k32 x 128)^T ----------------
__device__ __forceinline__ void compute32(
    uint32_t sb, int kbase,   // kbase = (s&1)*32 elements
    float acc[2][8][4], int wm, int wn, int aRow, int aKoff, int bRow, int bKoff)
{
#pragma unroll
    for (int ks = 0; ks < 2; ks++) {
        const int kb = kbase + 16 * ks;
        uint32_t ah[2][4], al[2][4];
#pragma unroll
        for (int mi = 0; mi < 2; mi++) {
            uint32_t off = (uint32_t)((32 * wm + 16 * mi + aRow) * 128 + (kb + aKoff) * 2);
            ldmx4(ah[mi], sb + OFF_AH + SWZ(off));
            ldmx4(al[mi], sb + OFF_AL + SWZ(off));
        }
#pragma unroll
        for (int np = 0; np < 4; np++) {
            uint32_t boff = (uint32_t)((64 * wn + 16 * np + bRow) * 128 + (kb + bKoff) * 2);
            uint32_t bh[4], bl[4];
            ldmx4(bh, sb + OFF_WH + SWZ(boff));
            ldmx4(bl, sb + OFF_WL + SWZ(boff));
#pragma unroll
            for (int mi = 0; mi < 2; mi++) {
                mma_bf16(acc[mi][2 * np],     ah[mi], bh[0], bh[1]);
                mma_bf16(acc[mi][2 * np],     ah[mi], bl[0], bl[1]);
                mma_bf16(acc[mi][2 * np],     al[mi], bh[0], bh[1]);
                mma_bf16(acc[mi][2 * np + 1], ah[mi], bh[2], bh[3]);
                mma_bf16(acc[mi][2 * np + 1], ah[mi], bl[2], bl[3]);
                mma_bf16(acc[mi][2 * np + 1], al[mi], bh[2], bh[3]);
            }
        }
    }
}

// ================= Kernel A: y = LeakyReLU(x_down @ W_lin + b_lin) -> gY =====
// 8 k32 steps; step s: W_lin chunk s>>1, half s&1; x_down cols 32s..32s+31.
__global__ __launch_bounds__(THREADS, 2)
void down_mlp_kernel(const float* __restrict__ x_down, const float* __restrict__ b_lin) {
    extern __shared__ char smem[];
    const uint32_t sb = smem_u32(smem);
    const int t = threadIdx.x;
    const int lane = t & 31;
    const int wid = t >> 5;
    const int wm = wid >> 1, wn = wid & 1;
    const int row0 = blockIdx.x * M_TILE;

    float* sB = (float*)(smem + OFF_B);
    if (t < 128) sB[t] = b_lin[t];

    const int aRow  = (lane < 16) ? lane : (lane - 16);
    const int aKoff = (lane < 16) ? 0 : 8;
    const int bRow  = (lane & 7) + ((lane >> 4) << 3);
    const int bKoff = ((lane >> 3) & 1) * 8;
    const int fg = lane >> 2, ft = lane & 3;

    float acc[2][8][4];
#pragma unroll
    for (int mi = 0; mi < 2; mi++)
#pragma unroll
        for (int ni = 0; ni < 8; ni++)
#pragma unroll
            for (int q = 0; q < 4; q++) acc[mi][ni][q] = 0.f;

    const float* xrow0 = x_down + (size_t)row0 * 256;

    // prologue: W piece 0 + x chunks 0,1
    stage_W32(sb, 0, 0, 0, t);
    stage_X32(sb, OFF_X0, xrow0, 256, 0, t);
    stage_X32(sb, OFF_X1, xrow0, 256, 1, t);
    cp_commit();
    cp_wait<0>();
    __syncthreads();
    convert32(smem, OFF_X0, 0, t);          // step 0 -> A.half0

#pragma unroll
    for (int s = 0; s < 8; s++) {
        if (s > 0) {
            cp_wait<0>();
            __syncthreads();
        } else {
            __syncthreads();                // order convert32(step0) before compute
        }
        if (s < 7) stage_W32(sb, 0, (s + 1) >> 1, (s + 1) & 1, t);
        if (s < 6) stage_X32(sb, (s & 1) ? OFF_X1 : OFF_X0, xrow0, 256, s + 2, t);
        cp_commit();
        if (s < 7) convert32(smem, ((s + 1) & 1) ? OFF_X1 : OFF_X0, (s + 1) & 1, t);
        compute32(sb, (s & 1) * 32, acc, wm, wn, aRow, aKoff, bRow, bKoff);
    }

    // epilogue: bias + LeakyReLU, split hi/lo -> gY
#pragma unroll
    for (int mi = 0; mi < 2; mi++) {
#pragma unroll
        for (int ni = 0; ni < 8; ni++) {
            int col = 64 * wn + 8 * ni + ft * 2;
            float b0 = sB[col], b1 = sB[col + 1];
            int rg = row0 + 32 * wm + 16 * mi + fg;
            float v0 = acc[mi][ni][0] + b0;  v0 = (v0 >= 0.f) ? v0 : 0.1f * v0;
            float v1 = acc[mi][ni][1] + b1;  v1 = (v1 >= 0.f) ? v1 : 0.1f * v1;
            float v2 = acc[mi][ni][2] + b0;  v2 = (v2 >= 0.f) ? v2 : 0.1f * v2;
            float v3 = acc[mi][ni][3] + b1;  v3 = (v3 >= 0.f) ? v3 : 0.1f * v3;
            float h0 = bf16r(v0), h1 = bf16r(v1), h2 = bf16r(v2), h3 = bf16r(v3);
            gY_hi[rg * 64 + (col >> 1)]       = pack_bf16x2(h0, h1);
            gY_lo[rg * 64 + (col >> 1)]       = pack_bf16x2(v0 - h0, v1 - h1);
            gY_hi[(rg + 8) * 64 + (col >> 1)] = pack_bf16x2(h2, h3);
            gY_lo[(rg + 8) * 64 + (col >> 1)] = pack_bf16x2(v2 - h2, v3 - h3);
        }
    }
}

// ================= Kernel B: out = LeakyReLU([x_up, gather(y)] @ W_fus + b_fus) =====
// 8 k32 steps: s=0..3 y (W_fus chunks 2,3), s=4..7 x_up (W_fus chunks 0,1).
__global__ __launch_bounds__(THREADS, 2)
void upsample_kernel(
    const float* __restrict__ x_up,    // [B*N_UP, 128]
    const int*   __restrict__ up_idx,  // [B*N_UP]
    const float* __restrict__ b_fus,
    float* __restrict__ out)           // [B*N_UP, 128]
{
    extern __shared__ char smem[];
    const uint32_t sb = smem_u32(smem);
    const int t = threadIdx.x;
    const int lane = t & 31;
    const int wid = t >> 5;
    const int wm = wid >> 1, wn = wid & 1;
    const int row0 = blockIdx.x * M_TILE;

    float* sB = (float*)(smem + OFF_B);
    if (t < 128) sB[t] = b_fus[t];

    // this thread's gather row
    const int srow = t >> 1;
    int r = row0 + srow;
    int idx = up_idx[r];
    if (idx < 0) idx = 0;
    if (idx >= N_DOWN) idx = N_DOWN - 1;
    const int yrow = (r >> 16) * N_DOWN + idx;

    const int aRow  = (lane < 16) ? lane : (lane - 16);
    const int aKoff = (lane < 16) ? 0 : 8;
    const int bRow  = (lane & 7) + ((lane >> 4) << 3);
    const int bKoff = ((lane >> 3) & 1) * 8;
    const int fg = lane >> 2, ft = lane & 3;

    float acc[2][8][4];
#pragma unroll
    for (int mi = 0; mi < 2; mi++)
#pragma unroll
        for (int ni = 0; ni < 8; ni++)
#pragma unroll
            for (int q = 0; q < 4; q++) acc[mi][ni][q] = 0.f;

    const float* xrow0 = x_up + (size_t)row0 * 128;

    // W piece p: chunk = p<4 ? 2+(p>>1) : (p-4)>>1 ; half = p&1 (source==dest half)
    // prologue: Ga = {W piece0, y slice0}; Gb = {x#0->X0, x#1->X1}
    stage_W32(sb, 1, 2, 0, t);
    stage_Y32(sb, yrow, 0, t);
    cp_commit();                          // Ga
    stage_X32(sb, OFF_X0, xrow0, 128, 0, t);
    stage_X32(sb, OFF_X1, xrow0, 128, 1, t);
    cp_commit();                          // Gb
    cp_wait<1>();                         // Ga done; Gb (DRAM x) still flying
    __syncthreads();

#pragma unroll
    for (int s = 0; s < 8; s++) {
        if (s > 0) {
            cp_wait<0>();
            __syncthreads();
        }
        // stage step s+1 (W lookahead 1; y lookahead 1)
        if (s < 7) {
            int p = s + 1;
            stage_W32(sb, 1, (p < 4) ? 2 + (p >> 1) : (p - 4) >> 1, p & 1, t);
            if (p <= 3) stage_Y32(sb, yrow, p, t);
        }
        // x refill after its convert freed the slot
        if (s == 4) stage_X32(sb, OFF_X0, xrow0, 128, 2, t);
        if (s == 5) stage_X32(sb, OFF_X1, xrow0, 128, 3, t);
        cp_commit();
        // convert for next step if it's an x step (x#j in X[j&1])
        if (s >= 3 && s < 7) {
            int j = s + 1 - 4;
            convert32(smem, (j & 1) ? OFF_X1 : OFF_X0, (s + 1) & 1, t);
        }
        compute32(sb, (s & 1) * 32, acc, wm, wn, aRow, aKoff, bRow, bKoff);
    }

    // epilogue: out = LeakyReLU(acc + b_fus)
#pragma unroll
    for (int mi = 0; mi < 2; mi++) {
#pragma unroll
        for (int ni = 0; ni < 8; ni++) {
            int col = 64 * wn + 8 * ni + ft * 2;
            float b0 = sB[col], b1 = sB[col + 1];
            int rg = row0 + 32 * wm + 16 * mi + fg;
            float v0 = acc[mi][ni][0] + b0;  v0 = (v0 >= 0.f) ? v0 : 0.1f * v0;
            float v1 = acc[mi][ni][1] + b1;  v1 = (v1 >= 0.f) ? v1 : 0.1f * v1;
            float v2 = acc[mi][ni][2] + b0;  v2 = (v2 >= 0.f) ? v2 : 0.1f * v2;
            float v3 = acc[mi][ni][3] + b1;  v3 = (v3 >= 0.f) ? v3 : 0.1f * v3;
            *(float2*)(out + (size_t)rg * C_UP + col)       = make_float2(v0, v1);
            *(float2*)(out + (size_t)(rg + 8) * C_UP + col) = make_float2(v2, v3);
        }
    }
}

extern "C" void kernel_launch(void* const* d_in, const int* in_sizes, int n_in,
                              void* d_out, int out_size) {
    const float* x_down = (const float*)d_in[0];
    const float* x_up   = (const float*)d_in[1];
    const int*   up_idx = (const int*)d_in[2];
    const float* W_lin  = (const float*)d_in[3];
    const float* b_lin  = (const float*)d_in[4];
    const float* W_fus  = (const float*)d_in[5];
    const float* b_fus  = (const float*)d_in[6];
    float* out = (float*)d_out;

    cudaFuncSetAttribute(down_mlp_kernel,
                         cudaFuncAttributeMaxDynamicSharedMemorySize, SMEM_TOTAL);
    cudaFuncSetAttribute(upsample_kernel,
                         cudaFuncAttributeMaxDynamicSharedMemorySize, SMEM_TOTAL);

    prep_weights<<<256, 256>>>(W_lin, W_fus);
    down_mlp_kernel<<<N_DOWN * 4 / M_TILE, THREADS, SMEM_TOTAL>>>(x_down, b_lin);
    upsample_kernel<<<N_UP * 4 / M_TILE, THREADS, SMEM_TOTAL>>>(x_up, up_idx, b_fus, out);
}

// round 14
// speedup vs baseline: 1.0714x; 1.0714x over previous
#include <cuda_runtime.h>
#include <cuda_bf16.h>
#include <cstdint>

// Fused (HMMA mma.sync bf16, 3-term split for fp32-grade accuracy):
// out = LeakyReLU([x_up, LeakyReLU(gather(x_down)@W_lin + b_lin)] @ W_fus + b_fus)
// Identity: MLP(gather(x)) == gather(MLP(x)) -> down-MLP computed once (4x less work).
// R12 = R10 structure (fastest measured) + kernel-B x-path staged via cp.async into a
// 16KB X slot with bounded waits (no exposed LDG converts; lookahead groups survive).
// NOTE: harness ptxas targets sm_103 (no 'a') -> tcgen05 unavailable; use mma.sync.

#define N_UP    65536
#define N_DOWN  16384
#define C_UP    128

#define M_TILE  128
#define THREADS 256

#define SWZ(x) ((x) ^ ((((uint32_t)(x)) >> 3) & 0x70))

// ---------------- kernel A smem layout (R10-identical) ----------------
#define AOFF_B    0
#define AOFF_WH   1024
#define AOFF_WL   (AOFF_WH + 16384)
#define AOFF_A0H  (AOFF_WL + 16384)
#define AOFF_A0L  (AOFF_A0H + 16384)
#define AOFF_A1H  (AOFF_A0L + 16384)
#define AOFF_A1L  (AOFF_A1H + 16384)
#define SMEM_A_TOTAL (AOFF_A1L + 16384)   // 99328

// ---------------- kernel B smem layout (bias via LDG; +X slot) ----------------
#define BOFF_WH   0
#define BOFF_WL   16384
#define BOFF_A0H  32768
#define BOFF_A0L  49152
#define BOFF_A1H  65536
#define BOFF_A1L  81920
#define BOFF_X    98304                    // fp32 [128][32] staging (16KB)
#define SMEM_B_TOTAL (BOFF_X + 16384)      // 114688 -> 2 CTAs/SM (2x115712<=233472)

// ---------------- device scratch ----------------
// Pre-split, pre-swizzled weight tile images: [layer][split][k64-chunk][16KB]
// Image layout: [n 0..127][k 0..63] bf16, 128B rows, SW128 swizzled.
__device__ __align__(16) unsigned char gW[2][2][4][16384];
// Down-MLP output y, pre-split bf16 hi/lo, row-major [B*N_DOWN][128] (uint32 = bf16x2)
__device__ __align__(16) unsigned int gY_hi[4194304];
__device__ __align__(16) unsigned int gY_lo[4194304];

// ---------------- helpers ----------------
__device__ __forceinline__ uint32_t smem_u32(const void* p) {
    uint32_t a;
    asm("{ .reg .u64 t; cvta.to.shared.u64 t, %1; cvt.u32.u64 %0, t; }" : "=r"(a) : "l"(p));
    return a;
}
__device__ __forceinline__ float bf16r(float x) {
    return __bfloat162float(__float2bfloat16(x));
}
__device__ __forceinline__ uint32_t pack_bf16x2(float lo, float hi) {
    uint32_t d;
    asm("cvt.rn.bf16x2.f32 %0, %1, %2;" : "=r"(d) : "f"(hi), "f"(lo));
    return d;
}
__device__ __forceinline__ void ldmx4(uint32_t* r, uint32_t a) {
    asm volatile("ldmatrix.sync.aligned.m8n8.x4.shared.b16 {%0,%1,%2,%3}, [%4];"
                 : "=r"(r[0]), "=r"(r[1]), "=r"(r[2]), "=r"(r[3]) : "r"(a));
}
__device__ __forceinline__ void mma_bf16(float* c, const uint32_t* a, uint32_t b0, uint32_t b1) {
    asm volatile("mma.sync.aligned.m16n8k16.row.col.f32.bf16.bf16.f32 "
                 "{%0,%1,%2,%3}, {%4,%5,%6,%7}, {%8,%9}, {%0,%1,%2,%3};"
                 : "+f"(c[0]), "+f"(c[1]), "+f"(c[2]), "+f"(c[3])
                 : "r"(a[0]), "r"(a[1]), "r"(a[2]), "r"(a[3]), "r"(b0), "r"(b1));
}
__device__ __forceinline__ void cp16(uint32_t dst, const void* src) {
    asm volatile("cp.async.cg.shared.global [%0], [%1], 16;" :: "r"(dst), "l"(src) : "memory");
}
__device__ __forceinline__ void cp_commit() {
    asm volatile("cp.async.commit_group;" ::: "memory");
}
template <int N>
__device__ __forceinline__ void cp_wait() {
    asm volatile("cp.async.wait_group %0;" :: "n"(N) : "memory");
}

// ---------------- prep ----------------
__global__ void prep_weights(const float* __restrict__ W_lin, const float* __restrict__ W_fus) {
    int tid = blockIdx.x * blockDim.x + threadIdx.x;
    for (int e = tid; e < 2 * 128 * 256; e += gridDim.x * blockDim.x) {
        int L = e >> 15;
        int r = e & 32767;
        int n = r >> 8;          // output col (N), 0..127
        int k = r & 255;         // K, 0..255
        const float* W = L ? W_fus : W_lin;
        float w = W[k * 128 + n];
        float h = bf16r(w);
        float l = w - h;
        int c = k >> 6, kk = k & 63;
        uint32_t a = SWZ((uint32_t)(n * 128 + kk * 2));
        *(unsigned short*)&gW[L][0][c][a] = __bfloat16_as_ushort(__float2bfloat16(h));
        *(unsigned short*)&gW[L][1][c][a] = __bfloat16_as_ushort(__float2bfloat16(l));
    }
}

// ---------------- staging ----------------
__device__ __forceinline__ void stage_W(uint32_t sb, int offWH, int offWL,
                                        int layer, int chunk, int t) {
    const char* srcH = (const char*)&gW[layer][0][chunk][0];
    const char* srcL = (const char*)&gW[layer][1][chunk][0];
#pragma unroll
    for (int i = 0; i < 4; i++) {
        int o = (t + 256 * i) * 16;
        cp16(sb + offWH + o, srcH + o);
        cp16(sb + offWL + o, srcL + o);
    }
}

// Gather pre-split y rows (bf16) straight into swizzled A images (k64 chunk).
__device__ __forceinline__ void stage_Yg(uint32_t sb, int offH, int offL,
                                         int yrow, int chunk, int t) {
    int srow = t >> 1, shalf = t & 1;
    size_t boff = (size_t)yrow * 256 + chunk * 128 + shalf * 64;   // bytes into gY
    const char* sh = (const char*)gY_hi + boff;
    const char* sl = (const char*)gY_lo + boff;
#pragma unroll
    for (int i = 0; i < 4; i++) {
        uint32_t d = SWZ((uint32_t)(srow * 128 + 64 * shalf + 16 * i));
        cp16(sb + offH + d, sh + 16 * i);
        cp16(sb + offL + d, sl + 16 * i);
    }
}

// fp32 k32 slice j (cols 32j..32j+31) of src -> X slot (plain layout, 128B rows).
__device__ __forceinline__ void stage_X32(uint32_t sb, int offX, const float* src0,
                                          int rowstride_f, int j, int t) {
    int srow = t >> 1, q = t & 1;
    const char* src = (const char*)(src0 + (size_t)srow * rowstride_f + j * 32 + q * 16);
    uint32_t dst = sb + offX + srow * 128 + q * 64;
#pragma unroll
    for (int i = 0; i < 4; i++) cp16(dst + 16 * i, src + 16 * i);
}

// Convert X slot fp32 [128][32] -> split bf16 into A image column half `half`.
// Each thread reads exactly the bytes it staged (srow = t>>1, q = t&1): no x-thread hazard.
__device__ __forceinline__ void convert32(char* smem, int offX, int offAH, int offAL,
                                          int half, int t) {
    int srow = t >> 1, q = t & 1;
    const float4* src = (const float4*)(smem + offX + srow * 128 + q * 64);
#pragma unroll
    for (int i = 0; i < 4; i++) {
        float4 v = src[i];
        float hx = bf16r(v.x), hy = bf16r(v.y), hz = bf16r(v.z), hw = bf16r(v.w);
        uint32_t a = SWZ((uint32_t)(srow * 128 + half * 64 + q * 32 + 8 * i));
        *(uint2*)(smem + offAH + a) = make_uint2(pack_bf16x2(hx, hy), pack_bf16x2(hz, hw));
        *(uint2*)(smem + offAL + a) = make_uint2(pack_bf16x2(v.x - hx, v.y - hy),
                                                 pack_bf16x2(v.z - hz, v.w - hw));
    }
}

// Direct LDG fp32 k64 chunk -> split bf16 -> swizzled A images (kernel A path).
__device__ __forceinline__ void convert_x(char* smem, int offH, int offL,
                                          const float* src0, int rowstride_f,
                                          int chunk, int t) {
    int srow = t >> 1, shalf = t & 1;
    const float4* src = (const float4*)(src0 + (size_t)srow * rowstride_f
                                        + chunk * 64 + shalf * 32);
#pragma unroll
    for (int i = 0; i < 8; i++) {
        float4 v = src[i];
        float hx = bf16r(v.x), hy = bf16r(v.y), hz = bf16r(v.z), hw = bf16r(v.w);
        uint32_t a = SWZ((uint32_t)(srow * 128 + 64 * shalf + 8 * i));
        *(uint2*)(smem + offH + a) = make_uint2(pack_bf16x2(hx, hy), pack_bf16x2(hz, hw));
        *(uint2*)(smem + offL + a) = make_uint2(pack_bf16x2(v.x - hx, v.y - hy),
                                                pack_bf16x2(v.z - hz, v.w - hw));
    }
}

// ---------------- per-chunk compute: acc += A(128x64) * W(64x128)^T ----------------
__device__ __forceinline__ void compute_chunk(
    uint32_t sb, int offAH, int offAL, int offWH, int offWL,
    float acc[2][8][4], int wm, int wn, int aRow, int aKoff, int bRow, int bKoff)
{
#pragma unroll
    for (int ks = 0; ks < 4; ks++) {
        const int kb = 16 * ks;
        uint32_t ah[2][4], al[2][4];
#pragma unroll
        for (int mi = 0; mi < 2; mi++) {
            uint32_t off = (uint32_t)((32 * wm + 16 * mi + aRow) * 128 + (kb + aKoff) * 2);
            ldmx4(ah[mi], sb + offAH + SWZ(off));
            ldmx4(al[mi], sb + offAL + SWZ(off));
        }
#pragma unroll
        for (int np = 0; np < 4; np++) {
            uint32_t boff = (uint32_t)((64 * wn + 16 * np + bRow) * 128 + (kb + bKoff) * 2);
            uint32_t bh[4], bl[4];
            ldmx4(bh, sb + offWH + SWZ(boff));
            ldmx4(bl, sb + offWL + SWZ(boff));
#pragma unroll
            for (int mi = 0; mi < 2; mi++) {
                mma_bf16(acc[mi][2 * np],     ah[mi], bh[0], bh[1]);
                mma_bf16(acc[mi][2 * np],     ah[mi], bl[0], bl[1]);
                mma_bf16(acc[mi][2 * np],     al[mi], bh[0], bh[1]);
                mma_bf16(acc[mi][2 * np + 1], ah[mi], bh[2], bh[3]);
                mma_bf16(acc[mi][2 * np + 1], ah[mi], bl[2], bl[3]);
                mma_bf16(acc[mi][2 * np + 1], al[mi], bh[2], bh[3]);
            }
        }
    }
}

// ================= Kernel A: y = LeakyReLU(x_down @ W_lin + b_lin) -> gY =====
// (R10-identical)
__global__ __launch_bounds__(THREADS, 2)
void down_mlp_kernel(const float* __restrict__ x_down, const float* __restrict__ b_lin) {
    extern __shared__ char smem[];
    const uint32_t sb = smem_u32(smem);
    const int t = threadIdx.x;
    const int lane = t & 31;
    const int wid = t >> 5;
    const int wm = wid >> 1, wn = wid & 1;
    const int row0 = blockIdx.x * M_TILE;

    float* sB = (float*)(smem + AOFF_B);
    if (t < 128) sB[t] = b_lin[t];

    const int aRow  = (lane < 16) ? lane : (lane - 16);
    const int aKoff = (lane < 16) ? 0 : 8;
    const int bRow  = (lane & 7) + ((lane >> 4) << 3);
    const int bKoff = ((lane >> 3) & 1) * 8;
    const int fg = lane >> 2, ft = lane & 3;

    float acc[2][8][4];
#pragma unroll
    for (int mi = 0; mi < 2; mi++)
#pragma unroll
        for (int ni = 0; ni < 8; ni++)
#pragma unroll
            for (int q = 0; q < 4; q++) acc[mi][ni][q] = 0.f;

    const int offAH[2] = {AOFF_A0H, AOFF_A1H};
    const int offAL[2] = {AOFF_A0L, AOFF_A1L};
    const float* xrow0 = x_down + (size_t)row0 * 256;

    stage_W(sb, AOFF_WH, AOFF_WL, 0, 0, t);
    cp_commit();
    convert_x(smem, AOFF_A0H, AOFF_A0L, xrow0, 256, 0, t);

#pragma unroll
    for (int c = 0; c < 4; c++) {
        cp_wait<0>();
        __syncthreads();
        int p = c & 1;
        compute_chunk(sb, offAH[p], offAL[p], AOFF_WH, AOFF_WL,
                      acc, wm, wn, aRow, aKoff, bRow, bKoff);
        __syncthreads();
        if (c < 3) {
            stage_W(sb, AOFF_WH, AOFF_WL, 0, c + 1, t);
            cp_commit();
            convert_x(smem, offAH[p ^ 1], offAL[p ^ 1], xrow0, 256, c + 1, t);
        }
    }

    // epilogue: bias + LeakyReLU, split hi/lo -> gY
#pragma unroll
    for (int mi = 0; mi < 2; mi++) {
#pragma unroll
        for (int ni = 0; ni < 8; ni++) {
            int col = 64 * wn + 8 * ni + ft * 2;
            float b0 = sB[col], b1 = sB[col + 1];
            int rg = row0 + 32 * wm + 16 * mi + fg;
            float v0 = acc[mi][ni][0] + b0;  v0 = (v0 >= 0.f) ? v0 : 0.1f * v0;
            float v1 = acc[mi][ni][1] + b1;  v1 = (v1 >= 0.f) ? v1 : 0.1f * v1;
            float v2 = acc[mi][ni][2] + b0;  v2 = (v2 >= 0.f) ? v2 : 0.1f * v2;
            float v3 = acc[mi][ni][3] + b1;  v3 = (v3 >= 0.f) ? v3 : 0.1f * v3;
            float h0 = bf16r(v0), h1 = bf16r(v1), h2 = bf16r(v2), h3 = bf16r(v3);
            gY_hi[rg * 64 + (col >> 1)]       = pack_bf16x2(h0, h1);
            gY_lo[rg * 64 + (col >> 1)]       = pack_bf16x2(v0 - h0, v1 - h1);
            gY_hi[(rg + 8) * 64 + (col >> 1)] = pack_bf16x2(h2, h3);
            gY_lo[(rg + 8) * 64 + (col >> 1)] = pack_bf16x2(v2 - h2, v3 - h3);
        }
    }
}

// ================= Kernel B: out = LeakyReLU([x_up, gather(y)] @ W_fus + b_fus) =====
// Steps: s0 y0xW2(A0), s1 y1xW3(A1), s2 x0xW0(A0), s3 x1xW1(A1).
// x fp32 halves prefetched into X slot one step ahead; converts read smem only.
__global__ __launch_bounds__(THREADS, 2)
void upsample_kernel(
    const float* __restrict__ x_up,    // [B*N_UP, 128]
    const int*   __restrict__ up_idx,  // [B*N_UP]
    const float* __restrict__ b_fus,
    float* __restrict__ out)           // [B*N_UP, 128]
{
    extern __shared__ char smem[];
    const uint32_t sb = smem_u32(smem);
    const int t = threadIdx.x;
    const int lane = t & 31;
    const int wid = t >> 5;
    const int wm = wid >> 1, wn = wid & 1;
    const int row0 = blockIdx.x * M_TILE;

    // this thread's gather row
    const int srow = t >> 1;
    int r = row0 + srow;
    int idx = up_idx[r];
    if (idx < 0) idx = 0;
    if (idx >= N_DOWN) idx = N_DOWN - 1;
    const int yrow = (r >> 16) * N_DOWN + idx;

    const int aRow  = (lane < 16) ? lane : (lane - 16);
    const int aKoff = (lane < 16) ? 0 : 8;
    const int bRow  = (lane & 7) + ((lane >> 4) << 3);
    const int bKoff = ((lane >> 3) & 1) * 8;
    const int fg = lane >> 2, ft = lane & 3;

    float acc[2][8][4];
#pragma unroll
    for (int mi = 0; mi < 2; mi++)
#pragma unroll
        for (int ni = 0; ni < 8; ni++)
#pragma unroll
            for (int q = 0; q < 4; q++) acc[mi][ni][q] = 0.f;

    const float* xrow0 = x_up + (size_t)row0 * 128;

    // ---- prologue ----
    stage_Yg(sb, BOFF_A0H, BOFF_A0L, yrow, 0, t);
    stage_W(sb, BOFF_WH, BOFF_WL, 1, 2, t);
    cp_commit();                                        // C1 {Y0, W2}
    stage_Yg(sb, BOFF_A1H, BOFF_A1L, yrow, 1, t);
    cp_commit();                                        // C2 {Y1}
    stage_X32(sb, BOFF_X, xrow0, 128, 0, t);
    cp_commit();                                        // C3 {x c0h0}

    // ---- s0: y0 x W2 (A0) ----
    cp_wait<2>();                                       // C1 done; C2,C3 in flight
    __syncthreads();
    compute_chunk(sb, BOFF_A0H, BOFF_A0L, BOFF_WH, BOFF_WL,
                  acc, wm, wn, aRow, aKoff, bRow, bKoff);

    // ---- s1: y1 x W3 (A1) ----
    __syncthreads();                                    // protect W slot + A0
    stage_W(sb, BOFF_WH, BOFF_WL, 1, 3, t);
    cp_commit();                                        // C4 {W3}
    cp_wait<0>();                                       // C2 (hidden), C3 (hidden), C4 (~L2)
    convert32(smem, BOFF_X, BOFF_A0H, BOFF_A0L, 0, t);  // c0h0 -> A0 half0
    stage_X32(sb, BOFF_X, xrow0, 128, 1, t);
    cp_commit();                                        // C5 {x c0h1}
    __syncthreads();
    compute_chunk(sb, BOFF_A1H, BOFF_A1L, BOFF_WH, BOFF_WL,
                  acc, wm, wn, aRow, aKoff, bRow, bKoff);

    // ---- s2: x0 x W0 (A0) ----
    __syncthreads();
    stage_W(sb, BOFF_WH, BOFF_WL, 1, 0, t);
    cp_commit();                                        // C6 {W0}
    cp_wait<0>();                                       // C5 (hidden by s1 compute), C6 (~L2)
    convert32(smem, BOFF_X, BOFF_A0H, BOFF_A0L, 1, t);  // c0h1 -> A0 half1
    stage_X32(sb, BOFF_X, xrow0, 128, 2, t);
    cp_commit();                                        // C7 {x c1h0}
    __syncthreads();
    compute_chunk(sb, BOFF_A0H, BOFF_A0L, BOFF_WH, BOFF_WL,
                  acc, wm, wn, aRow, aKoff, bRow, bKoff);

    // ---- s3: x1 x W1 (A1) ----
    __syncthreads();
    stage_W(sb, BOFF_WH, BOFF_WL, 1, 1, t);
    cp_commit();                                        // C8 {W1}
    cp_wait<0>();                                       // C7 (hidden by s2 compute), C8 (~L2)
    convert32(smem, BOFF_X, BOFF_A1H, BOFF_A1L, 0, t);  // c1h0 -> A1 half0
    stage_X32(sb, BOFF_X, xrow0, 128, 3, t);
    cp_commit();                                        // C9 {x c1h1}
    cp_wait<0>();                                       // C9 exposed (~1 DRAM round, once)
    convert32(smem, BOFF_X, BOFF_A1H, BOFF_A1L, 1, t);  // c1h1 -> A1 half1
    __syncthreads();
    compute_chunk(sb, BOFF_A1H, BOFF_A1L, BOFF_WH, BOFF_WL,
                  acc, wm, wn, aRow, aKoff, bRow, bKoff);

    // ---- epilogue: out = LeakyReLU(acc + b_fus); bias via LDG (L1-resident) ----
#pragma unroll
    for (int mi = 0; mi < 2; mi++) {
#pragma unroll
        for (int ni = 0; ni < 8; ni++) {
            int col = 64 * wn + 8 * ni + ft * 2;
            float b0 = b_fus[col], b1 = b_fus[col + 1];
            int rg = row0 + 32 * wm + 16 * mi + fg;
            float v0 = acc[mi][ni][0] + b0;  v0 = (v0 >= 0.f) ? v0 : 0.1f * v0;
            float v1 = acc[mi][ni][1] + b1;  v1 = (v1 >= 0.f) ? v1 : 0.1f * v1;
            float v2 = acc[mi][ni][2] + b0;  v2 = (v2 >= 0.f) ? v2 : 0.1f * v2;
            float v3 = acc[mi][ni][3] + b1;  v3 = (v3 >= 0.f) ? v3 : 0.1f * v3;
            *(float2*)(out + (size_t)rg * C_UP + col)       = make_float2(v0, v1);
            *(float2*)(out + (size_t)(rg + 8) * C_UP + col) = make_float2(v2, v3);
        }
    }
}

extern "C" void kernel_launch(void* const* d_in, const int* in_sizes, int n_in,
                              void* d_out, int out_size) {
    const float* x_down = (const float*)d_in[0];
    const float* x_up   = (const float*)d_in[1];
    const int*   up_idx = (const int*)d_in[2];
    const float* W_lin  = (const float*)d_in[3];
    const float* b_lin  = (const float*)d_in[4];
    const float* W_fus  = (const float*)d_in[5];
    const float* b_fus  = (const float*)d_in[6];
    float* out = (float*)d_out;

    cudaFuncSetAttribute(down_mlp_kernel,
                         cudaFuncAttributeMaxDynamicSharedMemorySize, SMEM_A_TOTAL);
    cudaFuncSetAttribute(upsample_kernel,
                         cudaFuncAttributeMaxDynamicSharedMemorySize, SMEM_B_TOTAL);

    prep_weights<<<256, 256>>>(W_lin, W_fus);
    down_mlp_kernel<<<N_DOWN * 4 / M_TILE, THREADS, SMEM_A_TOTAL>>>(x_down, b_lin);
    upsample_kernel<<<N_UP * 4 / M_TILE, THREADS, SMEM_B_TOTAL>>>(x_up, up_idx, b_fus, out);
}